// round 14
// baseline (speedup 1.0000x reference)
#include <cuda_runtime.h>
#include <cuda_fp16.h>
#include <cuda_fp8.h>
#include <cstdint>

#define BB 64
#define SS 576
#define DD 768
#define CC 200
#define NP 208             // padded class dim
#define MT 64              // s-rows per CTA (576 = 9*64, exact)
#define KC 32              // K chunk (elems = bytes in fp8)
#define NK 24              // 768/32
#define NSB 3              // B stages

#define WSCALE 32.0f       // attn_w pre-scale into e4m3 normal range
#define WINV   0.03125f

#define A8_STRIDE 48       // bytes per A row (32 data + 16 pad): LDSM conflict-free
#define B8_STRIDE 48       // bytes per B row

#define SZ_A8    (MT * A8_STRIDE)                       // 3072 per stage
#define SZ_BSTG  (NP * B8_STRIDE)                       // 9984 per stage
#define OFF_A8   0
#define OFF_B8   (2 * SZ_A8)                            // 6144
#define OFF_RS   (OFF_B8 + NSB * SZ_BSTG)               // 36096
#define OFF_CS   (OFF_RS + MT * 4)                      // 36352
#define SMEM_TOTAL (OFF_CS + NP * 4)                    // 37184 -> occ reg-bound 3

// e4m3 copy of attn_w * 32, zero-padded to NP rows (static scratch, no allocs)
__device__ uint8_t g_w8[NP * DD];

__device__ __forceinline__ uint32_t smem_u32(const void* p) {
    uint32_t a;
    asm("{ .reg .u64 t; cvta.to.shared.u64 t, %1; cvt.u32.u64 %0, t; }" : "=r"(a) : "l"(p));
    return a;
}
__device__ __forceinline__ void cp_async16(uint32_t dst, const void* src) {
    asm volatile("{ .reg .u64 g; cvta.to.global.u64 g, %1; cp.async.cg.shared.global [%0], [g], 16; }"
                 :: "r"(dst), "l"(src) : "memory");
}
#define CP_COMMIT() asm volatile("cp.async.commit_group;" ::: "memory")
#define CP_WAIT1()  asm volatile("cp.async.wait_group 1;" ::: "memory")

#define LDSM4(r0, r1, r2, r3, addr)                                           \
    asm volatile("ldmatrix.sync.aligned.m8n8.x4.shared.b16 {%0,%1,%2,%3}, [%4];" \
        : "=r"(r0), "=r"(r1), "=r"(r2), "=r"(r3) : "r"(addr))
#define LDSM2(r0, r1, addr)                                                   \
    asm volatile("ldmatrix.sync.aligned.m8n8.x2.shared.b16 {%0,%1}, [%2];"    \
        : "=r"(r0), "=r"(r1) : "r"(addr))

#define MMA8(c, a0, a1, a2, a3, b0, b1)                                       \
    asm volatile("mma.sync.aligned.m16n8k32.row.col.f32.e4m3.e4m3.f32 "       \
        "{%0,%1,%2,%3},{%4,%5,%6,%7},{%8,%9},{%0,%1,%2,%3};"                  \
        : "+f"((c)[0]), "+f"((c)[1]), "+f"((c)[2]), "+f"((c)[3])              \
        : "r"(a0), "r"(a1), "r"(a2), "r"(a3), "r"(b0), "r"(b1))

__device__ __forceinline__ float sigf(float x) { return 1.f / (1.f + __expf(-x)); }

__device__ __forceinline__ uint32_t pack4_e4m3(float a, float b, float c, float d) {
    uint32_t b0 = __nv_cvt_float_to_fp8(a, __NV_SATFINITE, __NV_E4M3);
    uint32_t b1 = __nv_cvt_float_to_fp8(b, __NV_SATFINITE, __NV_E4M3);
    uint32_t b2 = __nv_cvt_float_to_fp8(c, __NV_SATFINITE, __NV_E4M3);
    uint32_t b3 = __nv_cvt_float_to_fp8(d, __NV_SATFINITE, __NV_E4M3);
    return b0 | (b1 << 8) | (b2 << 16) | (b3 << 24);   // k ascending, low->high byte
}

// ---------------------------------------------------------------------------
// prep kernel: blocks [0,78): attn_w * 32 -> g_w8 (e4m3, zero-padded rows)
//              blocks [78,1678): global_scores = class_token @ gc_w^T + gc_b
// ---------------------------------------------------------------------------
__global__ void prep_kernel(const float* __restrict__ aw,
                            const float* __restrict__ ct,
                            const float* __restrict__ gcw,
                            const float* __restrict__ gcb,
                            float* __restrict__ out) {
    int bid = blockIdx.x;
    if (bid < 78) {
        int base = bid * 2048 + threadIdx.x * 8;   // 78*2048 = NP*DD
        #pragma unroll
        for (int i = 0; i < 8; ++i) {
            int idx = base + i;
            int c = idx / DD;
            float v = (c < CC) ? aw[idx] * WSCALE : 0.f;
            g_w8[idx] = __nv_cvt_float_to_fp8(v, __NV_SATFINITE, __NV_E4M3);
        }
    } else {
        int W = (bid - 78) * 8 + (threadIdx.x >> 5);   // 0..12799
        int lane = threadIdx.x & 31;
        int b = W & 63;
        int c = W >> 6;                                // 0..199
        const float* x = ct + (size_t)b * DD;
        const float* w = gcw + (size_t)c * DD;
        float acc = 0.f;
        #pragma unroll 4
        for (int d = lane; d < DD; d += 32) acc += x[d] * w[d];
        #pragma unroll
        for (int m = 16; m; m >>= 1) acc += __shfl_xor_sync(0xffffffffu, acc, m);
        if (lane == 0) out[b * CC + c] = acc + gcb[c];
    }
}

// ---------------------------------------------------------------------------
// attn kernel: logits = patch @ attn_w^T via fp8 e4m3 mma.sync m16n8k32,
//   out[b,c] += lam/(S*D) * sum_s sigmoid(logit + bias) * rowsum[b,s]
// CTA tile M=64 x N=208; warps 4(m) x 2(n); warp tile 16 x 104 (f32 acc).
// A: LDG f32 -> regs (1 iter ahead) -> cvt e4m3 -> STS (double buffer).
// B: cp.async fp8 (pre-converted), 3-stage ring. ONE barrier per iteration.
// ---------------------------------------------------------------------------
__global__ void __launch_bounds__(256, 3)
attn_kernel(const float* __restrict__ patch,
            const float* __restrict__ attn_b,
            const float* __restrict__ lam,
            float* __restrict__ out) {
    extern __shared__ __align__(16) char smem[];
    uint8_t* A8 = (uint8_t*)(smem + OFF_A8);
    float*   rs = (float*)(smem + OFF_RS);
    float*   colsum = (float*)(smem + OFF_CS);
    const uint32_t sb = smem_u32(smem);

    const int tid  = threadIdx.x;
    const int lane = tid & 31;
    const int warp = tid >> 5;
    const int wm   = warp >> 1;          // 0..3
    const int wn   = warp & 1;           // 0..1
    const int g    = lane >> 2;          // 0..7
    const int q    = lane & 3;           // 0..3

    const int b  = blockIdx.y;
    const int s0 = blockIdx.x * MT;

    if (tid < NP) colsum[tid] = 0.f;

    // A LDG mapping: 4 threads per row, 8 f32 each
    const int arow = tid >> 2;           // 0..63
    const int aseg = tid & 3;            // cols aseg*8 .. +7
    const float* gA = patch + ((size_t)b * SS + s0 + arow) * DD + aseg * 8;

    // ldmatrix per-lane byte offsets (48B rows: 16B-aligned, conflict-free)
    const uint32_t aoff = (uint32_t)(((lane & 7) + ((lane >> 3) & 1) * 8) * A8_STRIDE
                                     + ((lane >> 4) & 1) * 16);
    const uint32_t boff = (uint32_t)(((lane & 7) + ((lane >> 4) & 1) * 8) * B8_STRIDE
                                     + ((lane >> 3) & 1) * 16);

    float acc[13][4];
    #pragma unroll
    for (int j = 0; j < 13; ++j) {
        acc[j][0] = 0.f; acc[j][1] = 0.f; acc[j][2] = 0.f; acc[j][3] = 0.f;
    }
    float rsum = 0.f;

    auto issueB = [&](int kt) {
        uint32_t bdst = sb + OFF_B8 + (kt % NSB) * SZ_BSTG;
        #pragma unroll
        for (int i = 0; i < 2; ++i) {                   // 416 chunks of 16B
            int f = tid + 256 * i;
            if (f < NP * 2) {
                int row = f >> 1, cc = f & 1;
                cp_async16(bdst + row * B8_STRIDE + cc * 16,
                           g_w8 + (size_t)row * DD + kt * KC + cc * 16);
            }
        }
        CP_COMMIT();
    };

    // prologue: B[0], B[1] in flight; A[0] in registers
    issueB(0);
    issueB(1);
    float4 r0 = *reinterpret_cast<const float4*>(gA);
    float4 r1 = *reinterpret_cast<const float4*>(gA + 4);

    for (int kt = 0; kt < NK; ++kt) {
        // ---- convert regs -> A8[kt&1] (e4m3) + rowsum ----
        {
            rsum += (r0.x + r0.y) + (r0.z + r0.w) + (r1.x + r1.y) + (r1.z + r1.w);
            uint2 u;
            u.x = pack4_e4m3(r0.x, r0.y, r0.z, r0.w);
            u.y = pack4_e4m3(r1.x, r1.y, r1.z, r1.w);
            *reinterpret_cast<uint2*>(A8 + (kt & 1) * SZ_A8
                                      + arow * A8_STRIDE + aseg * 8) = u;
        }
        // ---- prefetch A[kt+1] into registers ----
        if (kt + 1 < NK) {
            const float* p = gA + (kt + 1) * KC;
            r0 = *reinterpret_cast<const float4*>(p);
            r1 = *reinterpret_cast<const float4*>(p + 4);
        }

        CP_WAIT1();                      // B[kt] arrived (pending <= {B[kt+1]})
        __syncthreads();                 // A8[kt&1] visible; B slot reuse safe

        if (kt + 2 < NK) issueB(kt + 2); else CP_COMMIT();

        // ---- mma: 13 nfrags, ONE k32 step per iteration ----
        const uint32_t abase = sb + OFF_A8 + (kt & 1) * SZ_A8
                             + wm * 16 * A8_STRIDE + aoff;
        const uint32_t bstage = sb + OFF_B8 + (kt % NSB) * SZ_BSTG
                              + wn * 104 * B8_STRIDE + boff;
        uint32_t a0, a1, a2, a3;
        LDSM4(a0, a1, a2, a3, abase);
        #pragma unroll
        for (int p = 0; p < 6; ++p) {
            uint32_t b0, b1, b2, b3;     // frags 2p (b0,b1) and 2p+1 (b2,b3)
            LDSM4(b0, b1, b2, b3, bstage + p * 16 * B8_STRIDE);
            MMA8(acc[2 * p],     a0, a1, a2, a3, b0, b1);
            MMA8(acc[2 * p + 1], a0, a1, a2, a3, b2, b3);
        }
        uint32_t b0, b1;
        LDSM2(b0, b1, bstage + 96 * B8_STRIDE);
        MMA8(acc[12], a0, a1, a2, a3, b0, b1);
    }

    // ---- rowsum reduce over the 4 threads per row ----
    rsum += __shfl_xor_sync(0xffffffffu, rsum, 1);
    rsum += __shfl_xor_sync(0xffffffffu, rsum, 2);
    if ((tid & 3) == 0) rs[arow] = rsum;
    __syncthreads();

    // ---- epilogue: sigmoid(logit/32 + bias) * rowsum, reduce over s ----
    const float rlo = rs[wm * 16 + g];
    const float rhi = rs[wm * 16 + g + 8];
    #pragma unroll
    for (int j = 0; j < 13; ++j) {
        const int ce = wn * 104 + j * 8 + 2 * q;
        float be = (ce     < CC) ? __ldg(&attn_b[ce])     : 0.f;
        float bo = (ce + 1 < CC) ? __ldg(&attn_b[ce + 1]) : 0.f;
        float pe = sigf(acc[j][0] * WINV + be) * rlo + sigf(acc[j][2] * WINV + be) * rhi;
        float po = sigf(acc[j][1] * WINV + bo) * rlo + sigf(acc[j][3] * WINV + bo) * rhi;
        #pragma unroll
        for (int m = 4; m < 32; m <<= 1) {
            pe += __shfl_xor_sync(0xffffffffu, pe, m);
            po += __shfl_xor_sync(0xffffffffu, po, m);
        }
        if (lane < 4) {                  // lane == q
            atomicAdd(&colsum[ce],     pe);
            atomicAdd(&colsum[ce + 1], po);
        }
    }
    __syncthreads();

    if (tid < CC) {
        float scale = __ldg(&lam[0]) * (1.f / (float)(SS * DD));
        atomicAdd(&out[b * CC + tid], scale * colsum[tid]);
    }
}

// ---------------------------------------------------------------------------
// kernel_launch
// inputs: 0 patch (64,576,768) f32 | 1 class_token (64,768) | 2 attn_w (200,768)
//         3 attn_b (200) | 4 gc_w (200,768) | 5 gc_b (200) | 6 lam (1)
// out: (64,200) f32
// ---------------------------------------------------------------------------
extern "C" void kernel_launch(void* const* d_in, const int* in_sizes, int n_in,
                              void* d_out, int out_size) {
    (void)in_sizes; (void)n_in; (void)out_size;
    const float* patch = (const float*)d_in[0];
    const float* ct    = (const float*)d_in[1];
    const float* aw    = (const float*)d_in[2];
    const float* ab    = (const float*)d_in[3];
    const float* gw    = (const float*)d_in[4];
    const float* gb    = (const float*)d_in[5];
    const float* lam   = (const float*)d_in[6];
    float* out = (float*)d_out;

    cudaFuncSetAttribute(attn_kernel, cudaFuncAttributeMaxDynamicSharedMemorySize,
                         SMEM_TOTAL);

    prep_kernel<<<78 + 1600, 256>>>(aw, ct, gw, gb, out);
    attn_kernel<<<dim3(SS / MT, BB), 256, SMEM_TOTAL>>>(patch, ab, lam, out);
}

// round 15
// speedup vs baseline: 1.1478x; 1.1478x over previous
#include <cuda_runtime.h>
#include <cuda_fp8.h>
#include <cstdint>

#define BB 64
#define SS 576
#define DD 768
#define CC 200
#define NP 208             // padded class dim
#define MT 64              // s-rows per CTA (576 = 9*64, exact)
#define KC 64              // K chunk (2 x k32 steps per barrier)
#define NK 12              // 768/64
#define NSB 3              // B stages

#define WSCALE 32.0f       // attn_w pre-scale into e4m3 normal range
#define WINV   0.03125f

#define B8_STRIDE 80       // bytes per B row (64 data + 16 pad): LDSM conflict-free

#define SZ_BSTG  (NP * B8_STRIDE)                       // 16640 per stage
#define OFF_B8   0
#define OFF_RS   (NSB * SZ_BSTG)                        // 49920
#define OFF_CS   (OFF_RS + MT * 4)                      // 50176
#define SMEM_TOTAL (OFF_CS + NP * 4)                    // 51008 -> occ 2

// e4m3 copy of attn_w * 32, zero-padded to NP rows (static scratch, no allocs)
__device__ uint8_t g_w8[NP * DD];

__device__ __forceinline__ uint32_t smem_u32(const void* p) {
    uint32_t a;
    asm("{ .reg .u64 t; cvta.to.shared.u64 t, %1; cvt.u32.u64 %0, t; }" : "=r"(a) : "l"(p));
    return a;
}
__device__ __forceinline__ void cp_async16(uint32_t dst, const void* src) {
    asm volatile("{ .reg .u64 g; cvta.to.global.u64 g, %1; cp.async.cg.shared.global [%0], [g], 16; }"
                 :: "r"(dst), "l"(src) : "memory");
}
#define CP_COMMIT() asm volatile("cp.async.commit_group;" ::: "memory")
#define CP_WAIT1()  asm volatile("cp.async.wait_group 1;" ::: "memory")

#define LDSM4(r0, r1, r2, r3, addr)                                           \
    asm volatile("ldmatrix.sync.aligned.m8n8.x4.shared.b16 {%0,%1,%2,%3}, [%4];" \
        : "=r"(r0), "=r"(r1), "=r"(r2), "=r"(r3) : "r"(addr))
#define LDSM2(r0, r1, addr)                                                   \
    asm volatile("ldmatrix.sync.aligned.m8n8.x2.shared.b16 {%0,%1}, [%2];"    \
        : "=r"(r0), "=r"(r1) : "r"(addr))

#define MMA8(c, a0, a1, a2, a3, b0, b1)                                       \
    asm volatile("mma.sync.aligned.m16n8k32.row.col.f32.e4m3.e4m3.f32 "       \
        "{%0,%1,%2,%3},{%4,%5,%6,%7},{%8,%9},{%0,%1,%2,%3};"                  \
        : "+f"((c)[0]), "+f"((c)[1]), "+f"((c)[2]), "+f"((c)[3])              \
        : "r"(a0), "r"(a1), "r"(a2), "r"(a3), "r"(b0), "r"(b1))

__device__ __forceinline__ float sigf(float x) { return 1.f / (1.f + __expf(-x)); }

__device__ __forceinline__ uint32_t pack4_e4m3(float4 v) {
    uint32_t b0 = __nv_cvt_float_to_fp8(v.x, __NV_SATFINITE, __NV_E4M3);
    uint32_t b1 = __nv_cvt_float_to_fp8(v.y, __NV_SATFINITE, __NV_E4M3);
    uint32_t b2 = __nv_cvt_float_to_fp8(v.z, __NV_SATFINITE, __NV_E4M3);
    uint32_t b3 = __nv_cvt_float_to_fp8(v.w, __NV_SATFINITE, __NV_E4M3);
    return b0 | (b1 << 8) | (b2 << 16) | (b3 << 24);   // k ascending, low->high byte
}

// ---------------------------------------------------------------------------
// prep kernel: blocks [0,78): attn_w * 32 -> g_w8 (e4m3, zero-padded rows)
//              blocks [78,1678): global_scores = class_token @ gc_w^T + gc_b
// ---------------------------------------------------------------------------
__global__ void prep_kernel(const float* __restrict__ aw,
                            const float* __restrict__ ct,
                            const float* __restrict__ gcw,
                            const float* __restrict__ gcb,
                            float* __restrict__ out) {
    int bid = blockIdx.x;
    if (bid < 78) {
        int base = bid * 2048 + threadIdx.x * 8;   // 78*2048 = NP*DD
        #pragma unroll
        for (int i = 0; i < 8; ++i) {
            int idx = base + i;
            int c = idx / DD;
            float v = (c < CC) ? aw[idx] * WSCALE : 0.f;
            g_w8[idx] = __nv_cvt_float_to_fp8(v, __NV_SATFINITE, __NV_E4M3);
        }
    } else {
        int W = (bid - 78) * 8 + (threadIdx.x >> 5);   // 0..12799
        int lane = threadIdx.x & 31;
        int b = W & 63;
        int c = W >> 6;                                // 0..199
        const float* x = ct + (size_t)b * DD;
        const float* w = gcw + (size_t)c * DD;
        float acc = 0.f;
        #pragma unroll 4
        for (int d = lane; d < DD; d += 32) acc += x[d] * w[d];
        #pragma unroll
        for (int m = 16; m; m >>= 1) acc += __shfl_xor_sync(0xffffffffu, acc, m);
        if (lane == 0) out[b * CC + c] = acc + gcb[c];
    }
}

// ---------------------------------------------------------------------------
// attn kernel: logits = patch @ attn_w^T via fp8 e4m3 mma.sync m16n8k32,
//   out[b,c] += lam/(S*D) * sum_s sigmoid(logit + bias) * rowsum[b,s]
// CTA tile M=64 x N=208; warps 4(m) x 2(n); warp tile 16 x 104 (f32 acc).
// A: per-warp direct LDG.128 in fragment layout -> register e4m3 pack.
//    NO smem, NO LDSM, no A-barrier. Prefetched one KC=64 iter ahead.
// B: cp.async fp8 (pre-converted), 3-stage ring, ONE barrier per KC=64.
// ---------------------------------------------------------------------------
__global__ void __launch_bounds__(256, 2)
attn_kernel(const float* __restrict__ patch,
            const float* __restrict__ attn_b,
            const float* __restrict__ lam,
            float* __restrict__ out) {
    extern __shared__ __align__(16) char smem[];
    float* rs     = (float*)(smem + OFF_RS);
    float* colsum = (float*)(smem + OFF_CS);
    const uint32_t sb = smem_u32(smem);

    const int tid  = threadIdx.x;
    const int lane = tid & 31;
    const int warp = tid >> 5;
    const int wm   = warp >> 1;          // 0..3
    const int wn   = warp & 1;           // 0..1
    const int g    = lane >> 2;          // 0..7
    const int q    = lane & 3;           // 0..3

    const int b  = blockIdx.y;
    const int s0 = blockIdx.x * MT;

    if (tid < NP) colsum[tid] = 0.f;

    // A fragment LDG bases: rows wm*16+g and +8, f32 col base q*4
    const float* gA0 = patch + ((size_t)b * SS + s0 + wm * 16 + g) * DD + q * 4;
    const float* gA1 = gA0 + 8 * (size_t)DD;

    // B ldmatrix per-lane byte offset (80B rows: 16B-aligned, conflict-free)
    const uint32_t boff = (uint32_t)(((lane & 7) + ((lane >> 4) & 1) * 8) * B8_STRIDE
                                     + ((lane >> 3) & 1) * 16);

    float acc[13][4];
    #pragma unroll
    for (int j = 0; j < 13; ++j) {
        acc[j][0] = 0.f; acc[j][1] = 0.f; acc[j][2] = 0.f; acc[j][3] = 0.f;
    }
    float rsum0 = 0.f, rsum1 = 0.f;

    auto issueB = [&](int kt) {
        uint32_t bdst = sb + OFF_B8 + (kt % NSB) * SZ_BSTG;
        #pragma unroll
        for (int i = 0; i < 4; ++i) {                   // 832 chunks of 16B
            int f = tid + 256 * i;
            if (f < NP * 4) {
                int row = f >> 2, cc = f & 3;
                cp_async16(bdst + row * B8_STRIDE + cc * 16,
                           g_w8 + (size_t)row * DD + kt * KC + cc * 16);
            }
        }
        CP_COMMIT();
    };

    // A staging: st[r2*4 + h*2 + half] (f32), one KC=64 iter ahead
    float4 st[8];
    auto loadA = [&](int kt) {
        #pragma unroll
        for (int h = 0; h < 2; ++h)
            #pragma unroll
            for (int hf = 0; hf < 2; ++hf) {
                int off = kt * KC + h * 32 + hf * 16;
                st[0 * 4 + h * 2 + hf] = *reinterpret_cast<const float4*>(gA0 + off);
                st[1 * 4 + h * 2 + hf] = *reinterpret_cast<const float4*>(gA1 + off);
            }
    };

    issueB(0);
    issueB(1);
    loadA(0);

    for (int kt = 0; kt < NK; ++kt) {
        // ---- pack staged A -> fragment regs (both k32 steps) + rowsum ----
        uint32_t pa[2][4];
        #pragma unroll
        for (int h = 0; h < 2; ++h) {
            pa[h][0] = pack4_e4m3(st[0 * 4 + h * 2 + 0]);   // a0: row g,  k 0-15
            pa[h][1] = pack4_e4m3(st[1 * 4 + h * 2 + 0]);   // a1: row g+8
            pa[h][2] = pack4_e4m3(st[0 * 4 + h * 2 + 1]);   // a2: row g,  k 16-31
            pa[h][3] = pack4_e4m3(st[1 * 4 + h * 2 + 1]);   // a3: row g+8
        }
        #pragma unroll
        for (int i = 0; i < 4; ++i) {
            float4 v0 = st[i], v1 = st[4 + i];
            rsum0 += (v0.x + v0.y) + (v0.z + v0.w);
            rsum1 += (v1.x + v1.y) + (v1.z + v1.w);
        }
        // ---- prefetch A[kt+1] (LDGs issued before any wait) ----
        if (kt + 1 < NK) loadA(kt + 1);

        CP_WAIT1();                      // B[kt] arrived (pending <= {B[kt+1]})
        __syncthreads();                 // all warps done with stage (kt-1)%NSB

        if (kt + 2 < NK) issueB(kt + 2); else CP_COMMIT();

        // ---- mma: 2 k32 steps x 13 nfrags, A from registers ----
        const uint32_t bstage = sb + OFF_B8 + (kt % NSB) * SZ_BSTG
                              + wn * 104 * B8_STRIDE + boff;
        #pragma unroll
        for (int h = 0; h < 2; ++h) {
            const uint32_t bs = bstage + h * 32;
            #pragma unroll
            for (int p = 0; p < 6; ++p) {
                uint32_t b0, b1, b2, b3;
                LDSM4(b0, b1, b2, b3, bs + p * 16 * B8_STRIDE);
                MMA8(acc[2 * p],     pa[h][0], pa[h][1], pa[h][2], pa[h][3], b0, b1);
                MMA8(acc[2 * p + 1], pa[h][0], pa[h][1], pa[h][2], pa[h][3], b2, b3);
            }
            uint32_t b0, b1;
            LDSM2(b0, b1, bs + 96 * B8_STRIDE);
            MMA8(acc[12], pa[h][0], pa[h][1], pa[h][2], pa[h][3], b0, b1);
        }
    }

    // ---- rowsum: reduce over q (lanes sharing a row) ----
    rsum0 += __shfl_xor_sync(0xffffffffu, rsum0, 1);
    rsum0 += __shfl_xor_sync(0xffffffffu, rsum0, 2);
    rsum1 += __shfl_xor_sync(0xffffffffu, rsum1, 1);
    rsum1 += __shfl_xor_sync(0xffffffffu, rsum1, 2);
    if (q == 0 && wn == 0) {
        rs[wm * 16 + g]     = rsum0;
        rs[wm * 16 + g + 8] = rsum1;
    }
    __syncthreads();

    // ---- epilogue: sigmoid(logit/32 + bias) * rowsum, reduce over s ----
    const float rlo = rs[wm * 16 + g];
    const float rhi = rs[wm * 16 + g + 8];
    #pragma unroll
    for (int j = 0; j < 13; ++j) {
        const int ce = wn * 104 + j * 8 + 2 * q;
        float be = (ce     < CC) ? __ldg(&attn_b[ce])     : 0.f;
        float bo = (ce + 1 < CC) ? __ldg(&attn_b[ce + 1]) : 0.f;
        float pe = sigf(acc[j][0] * WINV + be) * rlo + sigf(acc[j][2] * WINV + be) * rhi;
        float po = sigf(acc[j][1] * WINV + bo) * rlo + sigf(acc[j][3] * WINV + bo) * rhi;
        #pragma unroll
        for (int m = 4; m < 32; m <<= 1) {
            pe += __shfl_xor_sync(0xffffffffu, pe, m);
            po += __shfl_xor_sync(0xffffffffu, po, m);
        }
        if (lane < 4) {                  // lane == q
            atomicAdd(&colsum[ce],     pe);
            atomicAdd(&colsum[ce + 1], po);
        }
    }
    __syncthreads();

    if (tid < CC) {
        float scale = __ldg(&lam[0]) * (1.f / (float)(SS * DD));
        atomicAdd(&out[b * CC + tid], scale * colsum[tid]);
    }
}

// ---------------------------------------------------------------------------
// kernel_launch
// inputs: 0 patch (64,576,768) f32 | 1 class_token (64,768) | 2 attn_w (200,768)
//         3 attn_b (200) | 4 gc_w (200,768) | 5 gc_b (200) | 6 lam (1)
// out: (64,200) f32
// ---------------------------------------------------------------------------
extern "C" void kernel_launch(void* const* d_in, const int* in_sizes, int n_in,
                              void* d_out, int out_size) {
    (void)in_sizes; (void)n_in; (void)out_size;
    const float* patch = (const float*)d_in[0];
    const float* ct    = (const float*)d_in[1];
    const float* aw    = (const float*)d_in[2];
    const float* ab    = (const float*)d_in[3];
    const float* gw    = (const float*)d_in[4];
    const float* gb    = (const float*)d_in[5];
    const float* lam   = (const float*)d_in[6];
    float* out = (float*)d_out;

    cudaFuncSetAttribute(attn_kernel, cudaFuncAttributeMaxDynamicSharedMemorySize,
                         SMEM_TOTAL);

    prep_kernel<<<78 + 1600, 256>>>(aw, ct, gw, gb, out);
    attn_kernel<<<dim3(SS / MT, BB), 256, SMEM_TOTAL>>>(patch, ab, lam, out);
}